// round 5
// baseline (speedup 1.0000x reference)
#include <cuda_runtime.h>
#include <math.h>

#define BATCH 64
#define T 128
#define NS 32      // state dim
#define MD 8       // input dim
#define PD 16      // obs dim
#define ST 34      // padded stride (even -> float2-aligned) for 32-wide
#define SP 18      // padded stride for 16-wide
#define QVAR 0.01f
#define RVAR 0.01f

// Scratch (forward-pass products consumed later).
__device__ __align__(16) float g_muf [BATCH * T * NS];
__device__ __align__(16) float g_mup [BATCH * T * NS];
__device__ __align__(16) float g_Sigf[BATCH * T * NS * NS];
__device__ __align__(16) float g_Sigp[BATCH * T * NS * NS];
__device__ __align__(16) float g_J   [BATCH * T * NS * NS];  // J transposed: [t][k][i] = J[i][k]

// ============================ FORWARD FILTER ============================
__global__ __launch_bounds__(256, 1)
void fwd_kernel(const float* __restrict__ Y, const float* __restrict__ U,
                const float* __restrict__ A, const float* __restrict__ Bm,
                const float* __restrict__ C, const float* __restrict__ mu0,
                const float* __restrict__ Sig0, float* __restrict__ out)
{
    __shared__ __align__(16) float sAt[NS][ST];     // A(t)^T (k-major)
    __shared__ __align__(16) float sS0[NS][ST];     // Sigma0 (t=0 only)
    __shared__ __align__(16) float sT1[NS][ST];     // T1 transposed / P transposed
    __shared__ __align__(16) float fSp[NS][ST];     // Sigma_pred
    __shared__ __align__(16) float fCt[2][NS][SP];  // C^T double-buffered (k-major)
    __shared__ __align__(16) float fW [NS][SP];     // W = Sp C^T  [i][c]
    __shared__ __align__(16) float fWt[PD][ST];     // W^T [c][i]
    __shared__ __align__(16) float fKt[PD][ST];     // K^T [c][i]
    __shared__ __align__(16) float fKn[NS][SP];     // K   [k][c]
    __shared__ __align__(16) float fGt[PD][ST];     // (A' K)^T [c][i]
    __shared__ __align__(16) float fS [PD][SP];     // innovation cov (chol in place)
    __shared__ __align__(16) float fB [NS][MD];
    __shared__ float smu[NS], smup[NS], sr[PD], sy[PD], su[MD];
    __shared__ unsigned char mapR[136], mapC[136], mapR8[36], mapC8[36];

    const int b = blockIdx.x, tid = threadIdx.x;
    const int tr = tid >> 4, tc = tid & 15;

    if (tid == 0) {
        int e = 0;
        for (int r = 0; r < 16; ++r)
            for (int c = r; c < 16; ++c) { mapR[e] = (unsigned char)r; mapC[e] = (unsigned char)c; ++e; }
        e = 0;
        for (int r = 0; r < 8; ++r)
            for (int c = r; c < 8; ++c) { mapR8[e] = (unsigned char)r; mapC8[e] = (unsigned char)c; ++e; }
    }
    {
        const size_t o = (size_t)b * T;
        const float* A0 = A  + o * NS * NS;
        const float* C0 = C  + o * PD * NS;
        const float* B0 = Bm + o * NS * MD;
        for (int e = tid; e < NS * NS; e += 256) { sAt[e & 31][e >> 5] = A0[e]; sS0[e >> 5][e & 31] = Sig0[e]; }
        for (int e = tid; e < PD * NS; e += 256) fCt[0][e & 31][e >> 5] = C0[e];
        if (tid < NS * MD) fB[tid >> 3][tid & 7] = B0[tid];
        if (tid < PD) sy[tid] = Y[o * PD + tid];
        if (tid < MD) su[tid] = U[o * MD + tid];
        if (tid < NS) smu[tid] = mu0[tid];
    }
    __syncthreads();

    for (int t = 0; t < T; ++t) {
        const size_t bt = (size_t)b * T + t;
        const int cc = t & 1;

        // --- P1: T1^T (full at t=0; 16-deep update from P,G,W for t>=1) ; mu_p ---
        {
            const int i0 = 2 * tr, j0 = 2 * tc;
            if (t == 0) {
                float c00 = 0.f, c01 = 0.f, c10 = 0.f, c11 = 0.f;
                #pragma unroll 8
                for (int k = 0; k < NS; ++k) {
                    float2 a  = *(const float2*)&sAt[k][i0];
                    float2 bb = *(const float2*)&sS0[k][j0];
                    c00 += a.x * bb.x; c01 += a.x * bb.y; c10 += a.y * bb.x; c11 += a.y * bb.y;
                }
                sT1[j0][i0] = c00; sT1[j0 + 1][i0] = c01; sT1[j0][i0 + 1] = c10; sT1[j0 + 1][i0 + 1] = c11;
            } else {
                float c00 = sT1[j0][i0],     c01 = sT1[j0 + 1][i0];
                float c10 = sT1[j0][i0 + 1], c11 = sT1[j0 + 1][i0 + 1];
                #pragma unroll
                for (int k = 0; k < PD; ++k) {
                    float2 g = *(const float2*)&fGt[k][i0];
                    float2 w = *(const float2*)&fWt[k][j0];
                    c00 -= g.x * w.x; c01 -= g.x * w.y; c10 -= g.y * w.x; c11 -= g.y * w.y;
                }
                sT1[j0][i0] = c00; sT1[j0 + 1][i0] = c01; sT1[j0][i0 + 1] = c10; sT1[j0 + 1][i0 + 1] = c11;
            }
            if (tid < NS) {
                float acc = 0.f;
                #pragma unroll 8
                for (int k = 0; k < NS; ++k) acc += sAt[k][tid] * smu[k];
                #pragma unroll
                for (int k = 0; k < MD; ++k) acc += fB[tid][k] * su[k];
                smup[tid] = acc;
            }
        }
        __syncthreads();

        // --- P2: Sp = sym(T1 A^T)+Q [136] ; r [16] ; g_mup [32] ---
        if (tid < 136) {
            const int i0 = 2 * mapR[tid], j0 = 2 * mapC[tid];
            float c00 = 0.f, c01 = 0.f, c10 = 0.f, c11 = 0.f;
            #pragma unroll 8
            for (int k = 0; k < NS; ++k) {
                float2 a  = *(const float2*)&sT1[k][i0];
                float2 bb = *(const float2*)&sAt[k][j0];
                c00 += a.x * bb.x; c01 += a.x * bb.y; c10 += a.y * bb.x; c11 += a.y * bb.y;
            }
            if (i0 == j0) { c00 += QVAR; c11 += QVAR; float av = 0.5f * (c01 + c10); c01 = av; c10 = av; }
            fSp[i0][j0] = c00; fSp[i0][j0 + 1] = c01; fSp[i0 + 1][j0] = c10; fSp[i0 + 1][j0 + 1] = c11;
            if (i0 != j0) {
                fSp[j0][i0] = c00; fSp[j0 + 1][i0] = c01; fSp[j0][i0 + 1] = c10; fSp[j0 + 1][i0 + 1] = c11;
            }
        } else if (tid >= 240) {
            const int i = tid - 240;
            float acc = sy[i];
            #pragma unroll 8
            for (int k = 0; k < NS; ++k) acc -= fCt[cc][k][i] * smup[k];
            sr[i] = acc;
        } else if (tid >= 176 && tid < 208) {
            g_mup[bt * NS + (tid - 176)] = smup[tid - 176];
        }
        __syncthreads();

        // --- P3: W = Sp C^T (both layouts) [128] ; g_Sigp store [128] ---
        if (tid < 128) {
            const int i0 = 2 * (tid >> 3), j0 = 2 * (tid & 7);
            float c00 = 0.f, c01 = 0.f, c10 = 0.f, c11 = 0.f;
            #pragma unroll 8
            for (int k = 0; k < NS; ++k) {
                float2 a  = *(const float2*)&fSp[k][i0];
                float2 bb = *(const float2*)&fCt[cc][k][j0];
                c00 += a.x * bb.x; c01 += a.x * bb.y; c10 += a.y * bb.x; c11 += a.y * bb.y;
            }
            fW[i0][j0] = c00; fW[i0][j0 + 1] = c01; fW[i0 + 1][j0] = c10; fW[i0 + 1][j0 + 1] = c11;
            fWt[j0][i0] = c00; fWt[j0 + 1][i0] = c01; fWt[j0][i0 + 1] = c10; fWt[j0 + 1][i0 + 1] = c11;
        } else {
            float* gp = g_Sigp + bt * NS * NS;
            for (int e = tid - 128; e < NS * NS; e += 128) gp[e] = fSp[e >> 5][e & 31];
        }
        __syncthreads();

        // --- P4: S = sym(C W)+R [36] ; prefetch t+1 inputs [220] ---
        if (tid < 36) {
            const int i0 = 2 * mapR8[tid], j0 = 2 * mapC8[tid];
            float c00 = 0.f, c01 = 0.f, c10 = 0.f, c11 = 0.f;
            #pragma unroll 8
            for (int k = 0; k < NS; ++k) {
                float2 a  = *(const float2*)&fCt[cc][k][i0];
                float2 bb = *(const float2*)&fW[k][j0];
                c00 += a.x * bb.x; c01 += a.x * bb.y; c10 += a.y * bb.x; c11 += a.y * bb.y;
            }
            if (i0 == j0) { c00 += RVAR; c11 += RVAR; float av = 0.5f * (c01 + c10); c01 = av; c10 = av; }
            fS[i0][j0] = c00; fS[i0][j0 + 1] = c01; fS[i0 + 1][j0] = c10; fS[i0 + 1][j0 + 1] = c11;
            if (i0 != j0) {
                fS[j0][i0] = c00; fS[j0 + 1][i0] = c01; fS[j0][i0 + 1] = c10; fS[j0 + 1][i0 + 1] = c11;
            }
        } else if (t + 1 < T) {
            const size_t bt1 = bt + 1;
            const float* An = A  + bt1 * NS * NS;
            const float* Cn = C  + bt1 * PD * NS;
            const float* Bn = Bm + bt1 * NS * MD;
            const int q = tid - 36;
            for (int e = q; e < NS * NS; e += 220) sAt[e & 31][e >> 5] = An[e];
            for (int e = q; e < PD * NS; e += 220) fCt[cc ^ 1][e & 31][e >> 5] = Cn[e];
            for (int e = q; e < NS * MD; e += 220) fB[e >> 3][e & 7] = Bn[e];
            if (q < PD) sy[q] = Y[bt1 * PD + q];
            else if (q < PD + MD) su[q - PD] = U[bt1 * MD + (q - PD)];
        }
        __syncthreads();

        // --- P5: warp0 chol16+solve -> K ; warps1-7 compute P = A(t+1)*Sp(t) ---
        if (tid < 32) {
            const int i = tid;
            float dinv[PD];
            #pragma unroll
            for (int k = 0; k < PD; ++k) {
                float dkk = fS[k][k];
                float rs  = rsqrtf(dkk);
                dinv[k] = rs;
                __syncwarp();
                if (i == k) fS[k][k] = dkk * rs;
                if (i > k && i < PD) fS[i][k] *= rs;
                __syncwarp();
                if (i > k && i < PD) {
                    float lik = fS[i][k];
                    for (int j2 = k + 1; j2 <= i; ++j2) fS[i][j2] -= lik * fS[j2][k];
                }
                __syncwarp();
            }
            {
                float x[PD];
                #pragma unroll
                for (int r2 = 0; r2 < PD; ++r2) {
                    float a0 = fW[i][r2], a1 = 0.f;
                    #pragma unroll
                    for (int k = 0; k < r2; ++k) {
                        if (k & 1) a1 += fS[r2][k] * x[k];
                        else       a0 -= fS[r2][k] * x[k];
                    }
                    x[r2] = (a0 - a1) * dinv[r2];
                }
                #pragma unroll
                for (int r2 = PD - 1; r2 >= 0; --r2) {
                    float a0 = x[r2], a1 = 0.f;
                    #pragma unroll
                    for (int k = r2 + 1; k < PD; ++k) {
                        if (k & 1) a1 += fS[k][r2] * x[k];
                        else       a0 -= fS[k][r2] * x[k];
                    }
                    x[r2] = (a0 - a1) * dinv[r2];
                }
                #pragma unroll
                for (int r2 = 0; r2 < PD; ++r2) { fKt[r2][i] = x[r2]; fKn[i][r2] = x[r2]; }
            }
        } else if (t + 1 < T) {
            const int q = tid - 32;
            for (int e = q; e < 256; e += 224) {
                const int i0 = 2 * (e >> 4), j0 = 2 * (e & 15);
                float c00 = 0.f, c01 = 0.f, c10 = 0.f, c11 = 0.f;
                #pragma unroll 8
                for (int k = 0; k < NS; ++k) {
                    float2 a  = *(const float2*)&sAt[k][i0];   // A(t+1)^T
                    float2 bb = *(const float2*)&fSp[k][j0];
                    c00 += a.x * bb.x; c01 += a.x * bb.y; c10 += a.y * bb.x; c11 += a.y * bb.y;
                }
                sT1[j0][i0] = c00; sT1[j0 + 1][i0] = c01; sT1[j0][i0 + 1] = c10; sT1[j0 + 1][i0 + 1] = c11;
            }
        }
        __syncthreads();

        // --- P6: Sigf = sym(Sp - K W^T) [136] ; Gt = (A'K)^T [64] ; mu_f [32] ---
        {
            float* gf = g_Sigf + bt * NS * NS;
            float* ob = out + bt * (size_t)(NS * (NS + 1));
            if (tid < 136) {
                const int i0 = 2 * mapR[tid], j0 = 2 * mapC[tid];
                float c00 = fSp[i0][j0],     c01 = fSp[i0][j0 + 1];
                float c10 = fSp[i0 + 1][j0], c11 = fSp[i0 + 1][j0 + 1];
                #pragma unroll
                for (int k = 0; k < PD; ++k) {
                    float2 a  = *(const float2*)&fKt[k][i0];
                    float2 bb = *(const float2*)&fWt[k][j0];
                    c00 -= a.x * bb.x; c01 -= a.x * bb.y; c10 -= a.y * bb.x; c11 -= a.y * bb.y;
                }
                if (i0 == j0) { float av = 0.5f * (c01 + c10); c01 = av; c10 = av; }
                gf[i0 * NS + j0] = c00; gf[i0 * NS + j0 + 1] = c01;
                gf[(i0 + 1) * NS + j0] = c10; gf[(i0 + 1) * NS + j0 + 1] = c11;
                if (i0 != j0) {
                    gf[j0 * NS + i0] = c00; gf[(j0 + 1) * NS + i0] = c01;
                    gf[j0 * NS + i0 + 1] = c10; gf[(j0 + 1) * NS + i0 + 1] = c11;
                }
                if (t == T - 1) {
                    ob[i0 * (NS + 1) + 1 + j0] = c00; ob[i0 * (NS + 1) + 2 + j0] = c01;
                    ob[(i0 + 1) * (NS + 1) + 1 + j0] = c10; ob[(i0 + 1) * (NS + 1) + 2 + j0] = c11;
                    if (i0 != j0) {
                        ob[j0 * (NS + 1) + 1 + i0] = c00; ob[(j0 + 1) * (NS + 1) + 1 + i0] = c01;
                        ob[j0 * (NS + 1) + 2 + i0] = c10; ob[(j0 + 1) * (NS + 1) + 2 + i0] = c11;
                    }
                }
            } else if (tid < 200) {
                if (t + 1 < T) {
                    const int q = tid - 136;
                    const int c0 = 2 * (q >> 3), i0 = 4 * (q & 7);
                    float g00 = 0.f, g01 = 0.f, g02 = 0.f, g03 = 0.f;
                    float g10 = 0.f, g11 = 0.f, g12 = 0.f, g13 = 0.f;
                    #pragma unroll 8
                    for (int k = 0; k < NS; ++k) {
                        float2 kn = *(const float2*)&fKn[k][c0];
                        float2 a1 = *(const float2*)&sAt[k][i0];
                        float2 a2 = *(const float2*)&sAt[k][i0 + 2];
                        g00 += a1.x * kn.x; g01 += a1.y * kn.x; g02 += a2.x * kn.x; g03 += a2.y * kn.x;
                        g10 += a1.x * kn.y; g11 += a1.y * kn.y; g12 += a2.x * kn.y; g13 += a2.y * kn.y;
                    }
                    fGt[c0][i0] = g00; fGt[c0][i0 + 1] = g01; fGt[c0][i0 + 2] = g02; fGt[c0][i0 + 3] = g03;
                    fGt[c0 + 1][i0] = g10; fGt[c0 + 1][i0 + 1] = g11; fGt[c0 + 1][i0 + 2] = g12; fGt[c0 + 1][i0 + 3] = g13;
                }
            } else if (tid >= 224) {
                const int i = tid - 224;
                float acc = smup[i];
                #pragma unroll
                for (int k = 0; k < PD; ++k) acc += fKt[k][i] * sr[k];
                smu[i] = acc;
                g_muf[bt * NS + i] = acc;
                if (t == T - 1) ob[i * (NS + 1)] = acc;
            }
        }
        __syncthreads();
    }
}

// ============================ J PRECOMPUTE (fully parallel) ============================
// grid (BATCH, T-1), 32 threads. J_t = Sigf(t) A(t)^T Sigp(t+1)^{-1}, stored transposed.
__global__ __launch_bounds__(32, 1)
void jpre_kernel(const float* __restrict__ A)
{
    __shared__ __align__(16) float sl[NS][33];
    const int lane = threadIdx.x;
    const int b = blockIdx.x;
    const int t = blockIdx.y;                  // 0 .. T-2
    const size_t bt = (size_t)b * T + t;
    const float* Ag  = A      + bt * NS * NS;
    const float* Sfg = g_Sigf + bt * NS * NS;
    const float* Spg = g_Sigp + (bt + 1) * NS * NS;

    #pragma unroll
    for (int e = lane; e < NS * NS / 4; e += 32) {
        float4 v = ((const float4*)Ag)[e];
        int r = (4 * e) >> 5, c = (4 * e) & 31;
        sl[r][c] = v.x; sl[r][c + 1] = v.y; sl[r][c + 2] = v.z; sl[r][c + 3] = v.w;
    }
    float sf[NS];
    #pragma unroll
    for (int q = 0; q < 8; ++q) {
        float4 v = ((const float4*)(Sfg + lane * NS))[q];
        sf[4 * q] = v.x; sf[4 * q + 1] = v.y; sf[4 * q + 2] = v.z; sf[4 * q + 3] = v.w;
    }
    __syncwarp();
    float m[NS];
    #pragma unroll
    for (int r = 0; r < NS; ++r) {
        float a0 = 0.f, a1 = 0.f;
        #pragma unroll 8
        for (int k = 0; k < NS; k += 2) { a0 += sf[k] * sl[r][k]; a1 += sf[k + 1] * sl[r][k + 1]; }
        m[r] = a0 + a1;
    }
    __syncwarp();
    #pragma unroll
    for (int e = lane; e < NS * NS / 4; e += 32) {
        float4 v = ((const float4*)Spg)[e];
        int r = (4 * e) >> 5, c = (4 * e) & 31;
        sl[r][c] = v.x; sl[r][c + 1] = v.y; sl[r][c + 2] = v.z; sl[r][c + 3] = v.w;
    }
    __syncwarp();
    {
        const int i = lane;
        #pragma unroll 1
        for (int k = 0; k < NS; ++k) {
            float dkk = sl[k][k];
            float rs  = rsqrtf(dkk);
            __syncwarp();
            if (i == k) { sl[k][k] = dkk * rs; sl[k][32] = rs; }
            if (i > k) sl[i][k] *= rs;
            __syncwarp();
            if (i > k) {
                float lik = sl[i][k];
                for (int j2 = k + 1; j2 <= i; ++j2) sl[i][j2] -= lik * sl[j2][k];
            }
            __syncwarp();
        }
    }
    float x[NS];
    #pragma unroll
    for (int r = 0; r < NS; ++r) {
        float a0 = m[r], a1 = 0.f;
        #pragma unroll
        for (int k = 0; k < r; ++k) {
            if (k & 1) a1 += sl[r][k] * x[k];
            else       a0 -= sl[r][k] * x[k];
        }
        x[r] = (a0 - a1) * sl[r][32];
    }
    #pragma unroll
    for (int r = NS - 1; r >= 0; --r) {
        float a0 = x[r], a1 = 0.f;
        #pragma unroll
        for (int k = r + 1; k < NS; ++k) {
            if (k & 1) a1 += sl[k][r] * x[k];
            else       a0 -= sl[k][r] * x[k];
        }
        x[r] = (a0 - a1) * sl[r][32];
    }
    float* Jg = g_J + bt * NS * NS;
    #pragma unroll
    for (int k = 0; k < NS; ++k) Jg[k * NS + lane] = x[k];
}

// ============================ BACKWARD SMOOTHER ============================
__global__ __launch_bounds__(256, 1)
void bwd_kernel(float* __restrict__ out)
{
    __shared__ __align__(16) float sSig[NS][ST];   // smoothed carry
    __shared__ __align__(16) float sT1 [NS][ST];
    __shared__ __align__(16) float wJt[2][NS][ST], wSf[2][NS][ST], wSp[2][NS][ST];
    __shared__ float smuP[2][NS], smufB[2][NS], smupB[2][NS];
    __shared__ unsigned char mapR[136], mapC[136];

    const int b = blockIdx.x, tid = threadIdx.x;
    const int tr = tid >> 4, tc = tid & 15;

    if (tid == 0) {
        int e = 0;
        for (int r = 0; r < 16; ++r)
            for (int c = r; c < 16; ++c) { mapR[e] = (unsigned char)r; mapC[e] = (unsigned char)c; ++e; }
    }
    {
        const int t0 = T - 2, p0 = t0 & 1;
        const size_t bt  = (size_t)b * T + t0;
        const size_t btL = (size_t)b * T + (T - 1);
        const float* Sfg = g_Sigf + bt * NS * NS;
        const float* Spg = g_Sigp + (bt + 1) * NS * NS;
        const float* Jg  = g_J    + bt * NS * NS;
        const float* SfL = g_Sigf + btL * NS * NS;
        for (int e = tid; e < NS * NS; e += 256) {
            wSf[p0][e >> 5][e & 31] = Sfg[e];
            wSp[p0][e >> 5][e & 31] = Spg[e];
            wJt[p0][e >> 5][e & 31] = Jg[e];
            sSig[e >> 5][e & 31]    = SfL[e];
        }
        if (tid < NS) { smufB[p0][tid] = g_muf[bt * NS + tid]; smuP[(T - 1) & 1][tid] = g_muf[btL * NS + tid]; }
        else if (tid < 2 * NS) smupB[p0][tid - NS] = g_mup[(bt + 1) * NS + (tid - NS)];
    }
    __syncthreads();

    for (int t = T - 2; t >= 0; --t) {
        const size_t bt = (size_t)b * T + t;
        const int p = t & 1;
        float (*Jt)[ST] = wJt[p];
        float (*Sf)[ST] = wSf[p];
        float (*Sp)[ST] = wSp[p];
        float* ob = out + bt * (size_t)(NS * (NS + 1));

        // phaseA: T1^T = (J (Sig_s - Sp))^T
        {
            const int i0 = 2 * tr, j0 = 2 * tc;
            float c00 = 0.f, c01 = 0.f, c10 = 0.f, c11 = 0.f;
            #pragma unroll 8
            for (int k = 0; k < NS; ++k) {
                float2 a  = *(const float2*)&Jt[k][i0];
                float2 s1 = *(const float2*)&sSig[k][j0];
                float2 s2 = *(const float2*)&Sp[k][j0];
                float bx = s1.x - s2.x, by = s1.y - s2.y;
                c00 += a.x * bx; c01 += a.x * by; c10 += a.y * bx; c11 += a.y * by;
            }
            sT1[j0][i0] = c00; sT1[j0 + 1][i0] = c01; sT1[j0][i0 + 1] = c10; sT1[j0 + 1][i0 + 1] = c11;
        }
        __syncthreads();

        // phaseB: Sig_n = sym(Sf + T1 J^T) [136] ; mu_n [32] ; prefetch t-1 [88]
        if (tid < 136) {
            const int i0 = 2 * mapR[tid], j0 = 2 * mapC[tid];
            float c00 = Sf[i0][j0],     c01 = Sf[i0][j0 + 1];
            float c10 = Sf[i0 + 1][j0], c11 = Sf[i0 + 1][j0 + 1];
            #pragma unroll 8
            for (int k = 0; k < NS; ++k) {
                float2 a  = *(const float2*)&sT1[k][i0];
                float2 bb = *(const float2*)&Jt[k][j0];
                c00 += a.x * bb.x; c01 += a.x * bb.y; c10 += a.y * bb.x; c11 += a.y * bb.y;
            }
            if (i0 == j0) { float av = 0.5f * (c01 + c10); c01 = av; c10 = av; }
            sSig[i0][j0] = c00; sSig[i0][j0 + 1] = c01; sSig[i0 + 1][j0] = c10; sSig[i0 + 1][j0 + 1] = c11;
            ob[i0 * (NS + 1) + 1 + j0] = c00; ob[i0 * (NS + 1) + 2 + j0] = c01;
            ob[(i0 + 1) * (NS + 1) + 1 + j0] = c10; ob[(i0 + 1) * (NS + 1) + 2 + j0] = c11;
            if (i0 != j0) {
                sSig[j0][i0] = c00; sSig[j0 + 1][i0] = c01; sSig[j0][i0 + 1] = c10; sSig[j0 + 1][i0 + 1] = c11;
                ob[j0 * (NS + 1) + 1 + i0] = c00; ob[(j0 + 1) * (NS + 1) + 1 + i0] = c01;
                ob[j0 * (NS + 1) + 2 + i0] = c10; ob[(j0 + 1) * (NS + 1) + 2 + i0] = c11;
            }
        } else if (tid < 168) {
            const int i = tid - 136;
            float acc = smufB[p][i];
            #pragma unroll 8
            for (int k = 0; k < NS; ++k) acc += Jt[k][i] * (smuP[p ^ 1][k] - smupB[p][k]);
            smuP[p][i] = acc;
            ob[i * (NS + 1)] = acc;
        } else if (t > 0) {
            const int q = tid - 168;
            const size_t btm = bt - 1;
            const float* Sfg = g_Sigf + btm * NS * NS;
            const float* Spg = g_Sigp + bt * NS * NS;
            const float* Jg  = g_J    + btm * NS * NS;
            const int pn = p ^ 1;
            for (int e = q; e < NS * NS; e += 88) {
                wSf[pn][e >> 5][e & 31] = Sfg[e];
                wSp[pn][e >> 5][e & 31] = Spg[e];
                wJt[pn][e >> 5][e & 31] = Jg[e];
            }
            if (q < NS) smufB[pn][q] = g_muf[btm * NS + q];
            else if (q < 2 * NS) smupB[pn][q - NS] = g_mup[bt * NS + (q - NS)];
        }
        __syncthreads();
    }
}

extern "C" void kernel_launch(void* const* d_in, const int* in_sizes, int n_in,
                              void* d_out, int out_size)
{
    const float* Y    = (const float*)d_in[0];
    const float* U    = (const float*)d_in[1];
    const float* A    = (const float*)d_in[2];
    const float* Bm   = (const float*)d_in[3];
    const float* C    = (const float*)d_in[4];
    const float* mu0  = (const float*)d_in[5];
    const float* Sig0 = (const float*)d_in[6];
    float* out = (float*)d_out;

    fwd_kernel<<<BATCH, 256>>>(Y, U, A, Bm, C, mu0, Sig0, out);
    jpre_kernel<<<dim3(BATCH, T - 1), 32>>>(A);
    bwd_kernel<<<BATCH, 256>>>(out);
}

// round 9
// speedup vs baseline: 1.1756x; 1.1756x over previous
#include <cuda_runtime.h>
#include <math.h>

#define BATCH 64
#define T 128
#define NS 32
#define MD 8
#define PD 16
#define ST 34      // padded stride (even -> float2-aligned) for 32-wide
#define SP 18      // padded stride for 16-wide
#define QVAR 0.01f
#define RVAR 0.01f

#define TBAR(id) asm volatile("bar.sync %0, %1;" :: "r"(id), "r"(256) : "memory")

// Scratch (forward-pass products consumed later).
__device__ __align__(16) float g_muf [BATCH * T * NS];
__device__ __align__(16) float g_mup [BATCH * T * NS];
__device__ __align__(16) float g_Sigf[BATCH * T * NS * NS];
__device__ __align__(16) float g_Sigp[BATCH * T * NS * NS];
__device__ __align__(16) float g_J   [BATCH * T * NS * NS];  // J transposed: [t][k][i] = J[i][k]

struct __align__(16) FwdS {
    float At [NS][ST];   // A^T (k-major)
    float Sig[NS][ST];   // carry Sigma_f (init Sigma0)
    float T1 [NS][ST];   // (A*Sig)^T
    float Sp [NS][ST];   // Sigma_pred
    float Ct [NS][SP];   // C^T (k-major)
    float W  [NS][SP];   // W = Sp C^T
    float Wt [PD][ST];   // W^T
    float Kt [PD][ST];   // K^T
    float S  [PD][SP];   // innovation cov (chol in place)
    float B  [NS][MD];
    float mu[NS], mup[NS], r[PD], y[PD], uu[MD];
    float pad[8];
};

struct __align__(16) BwdS {
    float Sig[NS][ST];   // smoothed carry
    float T1 [NS][ST];
    float Jt[2][NS][ST], Sf[2][NS][ST], Sp[2][NS][ST];
    float muP[2][NS], mufB[2][NS], mupB[2][NS];
    float pad[8];
};

// ============================ FORWARD FILTER (2 teams / CTA) ============================
__global__ __launch_bounds__(512, 1)
void fwd_kernel(const float* __restrict__ Y, const float* __restrict__ U,
                const float* __restrict__ A, const float* __restrict__ Bm,
                const float* __restrict__ C, const float* __restrict__ mu0,
                const float* __restrict__ Sig0, float* __restrict__ out)
{
    extern __shared__ __align__(16) char dyn[];
    __shared__ unsigned char mapR[136], mapC[136], mapR8[36], mapC8[36];

    const int tid  = threadIdx.x;
    const int team = tid >> 8, rt = tid & 255;
    const int b    = blockIdx.x * 2 + team;
    const int bar  = 1 + team;
    FwdS& s = ((FwdS*)dyn)[team];
    const int tr = rt >> 4, tc = rt & 15;

    if (tid == 0) {
        int e = 0;
        for (int r = 0; r < 16; ++r)
            for (int c = r; c < 16; ++c) { mapR[e] = (unsigned char)r; mapC[e] = (unsigned char)c; ++e; }
        e = 0;
        for (int r = 0; r < 8; ++r)
            for (int c = r; c < 8; ++c) { mapR8[e] = (unsigned char)r; mapC8[e] = (unsigned char)c; ++e; }
    }
    {
        const size_t o = (size_t)b * T;
        const float* A0 = A  + o * NS * NS;
        const float* C0 = C  + o * PD * NS;
        const float* B0 = Bm + o * NS * MD;
        for (int e = rt; e < NS * NS; e += 256) { s.At[e & 31][e >> 5] = A0[e]; s.Sig[e >> 5][e & 31] = Sig0[e]; }
        for (int e = rt; e < PD * NS; e += 256) s.Ct[e & 31][e >> 5] = C0[e];
        s.B[rt >> 3][rt & 7] = B0[rt];                 // NS*MD = 256 elements
        if (rt < PD) s.y[rt] = Y[o * PD + rt];
        else if (rt < PD + MD) s.uu[rt - PD] = U[o * MD + (rt - PD)];
        if (rt >= 32 && rt < 64) s.mu[rt - 32] = mu0[rt - 32];
    }
    __syncthreads();

    for (int t = 0; t < T; ++t) {
        const size_t bt = (size_t)b * T + t;

        // --- P1: T1^T = (A * Sig)^T (256 tiles, 32-deep) ; mu_p (warp0) ---
        {
            const int i0 = 2 * tr, j0 = 2 * tc;
            float c00 = 0.f, c01 = 0.f, c10 = 0.f, c11 = 0.f;
            #pragma unroll 8
            for (int k = 0; k < NS; ++k) {
                float2 a  = *(const float2*)&s.At[k][i0];
                float2 bb = *(const float2*)&s.Sig[k][j0];
                c00 += a.x * bb.x; c01 += a.x * bb.y; c10 += a.y * bb.x; c11 += a.y * bb.y;
            }
            s.T1[j0][i0] = c00; s.T1[j0 + 1][i0] = c01; s.T1[j0][i0 + 1] = c10; s.T1[j0 + 1][i0 + 1] = c11;
            if (rt < NS) {
                float acc = 0.f;
                #pragma unroll 8
                for (int k = 0; k < NS; ++k) acc += s.At[k][rt] * s.mu[k];
                #pragma unroll
                for (int k = 0; k < MD; ++k) acc += s.B[rt][k] * s.uu[k];
                s.mup[rt] = acc;
            }
        }
        TBAR(bar);

        // --- P2: Sp = sym(T1 A^T)+Q [136] ; r [16] ; g_mup [32] ---
        if (rt < 136) {
            const int i0 = 2 * mapR[rt], j0 = 2 * mapC[rt];
            float c00 = 0.f, c01 = 0.f, c10 = 0.f, c11 = 0.f;
            #pragma unroll 8
            for (int k = 0; k < NS; ++k) {
                float2 a  = *(const float2*)&s.T1[k][i0];
                float2 bb = *(const float2*)&s.At[k][j0];
                c00 += a.x * bb.x; c01 += a.x * bb.y; c10 += a.y * bb.x; c11 += a.y * bb.y;
            }
            if (i0 == j0) { c00 += QVAR; c11 += QVAR; float av = 0.5f * (c01 + c10); c01 = av; c10 = av; }
            s.Sp[i0][j0] = c00; s.Sp[i0][j0 + 1] = c01; s.Sp[i0 + 1][j0] = c10; s.Sp[i0 + 1][j0 + 1] = c11;
            if (i0 != j0) {
                s.Sp[j0][i0] = c00; s.Sp[j0 + 1][i0] = c01; s.Sp[j0][i0 + 1] = c10; s.Sp[j0 + 1][i0 + 1] = c11;
            }
        } else if (rt >= 240) {
            const int i = rt - 240;
            float acc = s.y[i];
            #pragma unroll 8
            for (int k = 0; k < NS; ++k) acc -= s.Ct[k][i] * s.mup[k];
            s.r[i] = acc;
        } else if (rt >= 176 && rt < 208) {
            g_mup[bt * NS + (rt - 176)] = s.mup[rt - 176];
        }
        TBAR(bar);

        // --- P3: W = Sp C^T (both layouts) [128] ; g_Sigp store [128] ---
        if (rt < 128) {
            const int i0 = 2 * (rt >> 3), j0 = 2 * (rt & 7);
            float c00 = 0.f, c01 = 0.f, c10 = 0.f, c11 = 0.f;
            #pragma unroll 8
            for (int k = 0; k < NS; ++k) {
                float2 a  = *(const float2*)&s.Sp[k][i0];
                float2 bb = *(const float2*)&s.Ct[k][j0];
                c00 += a.x * bb.x; c01 += a.x * bb.y; c10 += a.y * bb.x; c11 += a.y * bb.y;
            }
            s.W[i0][j0] = c00; s.W[i0][j0 + 1] = c01; s.W[i0 + 1][j0] = c10; s.W[i0 + 1][j0 + 1] = c11;
            s.Wt[j0][i0] = c00; s.Wt[j0 + 1][i0] = c01; s.Wt[j0][i0 + 1] = c10; s.Wt[j0 + 1][i0 + 1] = c11;
        } else {
            float* gp = g_Sigp + bt * NS * NS;
            for (int e = rt - 128; e < NS * NS; e += 128) gp[e] = s.Sp[e >> 5][e & 31];
        }
        TBAR(bar);

        // --- P4: S = sym(C W)+R [36] ---
        if (rt < 36) {
            const int i0 = 2 * mapR8[rt], j0 = 2 * mapC8[rt];
            float c00 = 0.f, c01 = 0.f, c10 = 0.f, c11 = 0.f;
            #pragma unroll 8
            for (int k = 0; k < NS; ++k) {
                float2 a  = *(const float2*)&s.Ct[k][i0];
                float2 bb = *(const float2*)&s.W[k][j0];
                c00 += a.x * bb.x; c01 += a.x * bb.y; c10 += a.y * bb.x; c11 += a.y * bb.y;
            }
            if (i0 == j0) { c00 += RVAR; c11 += RVAR; float av = 0.5f * (c01 + c10); c01 = av; c10 = av; }
            s.S[i0][j0] = c00; s.S[i0][j0 + 1] = c01; s.S[i0 + 1][j0] = c10; s.S[i0 + 1][j0 + 1] = c11;
            if (i0 != j0) {
                s.S[j0][i0] = c00; s.S[j0 + 1][i0] = c01; s.S[j0][i0 + 1] = c10; s.S[j0 + 1][i0 + 1] = c11;
            }
        }
        TBAR(bar);

        // --- P5: warp0 chol16+solve -> Kt ; other warps prefetch t+1 ---
        if (rt < 32) {
            const int i = rt;
            float dinv[PD];
            #pragma unroll
            for (int k = 0; k < PD; ++k) {
                float dkk = s.S[k][k];
                float rs  = rsqrtf(dkk);
                dinv[k] = rs;
                __syncwarp();
                if (i == k) s.S[k][k] = dkk * rs;
                if (i > k && i < PD) s.S[i][k] *= rs;
                __syncwarp();
                if (i > k && i < PD) {
                    float lik = s.S[i][k];
                    for (int j2 = k + 1; j2 <= i; ++j2) s.S[i][j2] -= lik * s.S[j2][k];
                }
                __syncwarp();
            }
            {
                float x[PD];
                #pragma unroll
                for (int r2 = 0; r2 < PD; ++r2) {
                    float a0 = s.W[i][r2], a1 = 0.f;
                    #pragma unroll
                    for (int k = 0; k < r2; ++k) {
                        if (k & 1) a1 += s.S[r2][k] * x[k];
                        else       a0 -= s.S[r2][k] * x[k];
                    }
                    x[r2] = (a0 - a1) * dinv[r2];
                }
                #pragma unroll
                for (int r2 = PD - 1; r2 >= 0; --r2) {
                    float a0 = x[r2], a1 = 0.f;
                    #pragma unroll
                    for (int k = r2 + 1; k < PD; ++k) {
                        if (k & 1) a1 += s.S[k][r2] * x[k];
                        else       a0 -= s.S[k][r2] * x[k];
                    }
                    x[r2] = (a0 - a1) * dinv[r2];
                }
                #pragma unroll
                for (int r2 = 0; r2 < PD; ++r2) s.Kt[r2][i] = x[r2];
            }
        } else if (t + 1 < T) {
            const size_t bt1 = bt + 1;
            const float* An = A  + bt1 * NS * NS;
            const float* Cn = C  + bt1 * PD * NS;
            const float* Bn = Bm + bt1 * NS * MD;
            const int q = rt - 32;
            for (int e = q; e < NS * NS; e += 224) s.At[e & 31][e >> 5] = An[e];
            for (int e = q; e < PD * NS; e += 224) s.Ct[e & 31][e >> 5] = Cn[e];
            for (int e = q; e < NS * MD; e += 224) s.B[e >> 3][e & 7] = Bn[e];
            if (q < PD) s.y[q] = Y[bt1 * PD + q];
            else if (q < PD + MD) s.uu[q - PD] = U[bt1 * MD + (q - PD)];
        }
        TBAR(bar);

        // --- P6: Sigf = sym(Sp - K W^T) [136] ; mu_f [32] ---
        {
            float* gf = g_Sigf + bt * NS * NS;
            float* ob = out + bt * (size_t)(NS * (NS + 1));
            if (rt < 136) {
                const int i0 = 2 * mapR[rt], j0 = 2 * mapC[rt];
                float c00 = s.Sp[i0][j0],     c01 = s.Sp[i0][j0 + 1];
                float c10 = s.Sp[i0 + 1][j0], c11 = s.Sp[i0 + 1][j0 + 1];
                #pragma unroll
                for (int k = 0; k < PD; ++k) {
                    float2 a  = *(const float2*)&s.Kt[k][i0];
                    float2 bb = *(const float2*)&s.Wt[k][j0];
                    c00 -= a.x * bb.x; c01 -= a.x * bb.y; c10 -= a.y * bb.x; c11 -= a.y * bb.y;
                }
                if (i0 == j0) { float av = 0.5f * (c01 + c10); c01 = av; c10 = av; }
                s.Sig[i0][j0] = c00; s.Sig[i0][j0 + 1] = c01; s.Sig[i0 + 1][j0] = c10; s.Sig[i0 + 1][j0 + 1] = c11;
                gf[i0 * NS + j0] = c00; gf[i0 * NS + j0 + 1] = c01;
                gf[(i0 + 1) * NS + j0] = c10; gf[(i0 + 1) * NS + j0 + 1] = c11;
                if (i0 != j0) {
                    s.Sig[j0][i0] = c00; s.Sig[j0 + 1][i0] = c01; s.Sig[j0][i0 + 1] = c10; s.Sig[j0 + 1][i0 + 1] = c11;
                    gf[j0 * NS + i0] = c00; gf[(j0 + 1) * NS + i0] = c01;
                    gf[j0 * NS + i0 + 1] = c10; gf[(j0 + 1) * NS + i0 + 1] = c11;
                }
                if (t == T - 1) {
                    ob[i0 * (NS + 1) + 1 + j0] = c00; ob[i0 * (NS + 1) + 2 + j0] = c01;
                    ob[(i0 + 1) * (NS + 1) + 1 + j0] = c10; ob[(i0 + 1) * (NS + 1) + 2 + j0] = c11;
                    if (i0 != j0) {
                        ob[j0 * (NS + 1) + 1 + i0] = c00; ob[(j0 + 1) * (NS + 1) + 1 + i0] = c01;
                        ob[j0 * (NS + 1) + 2 + i0] = c10; ob[(j0 + 1) * (NS + 1) + 2 + i0] = c11;
                    }
                }
            } else if (rt >= 224) {
                const int i = rt - 224;
                float acc = s.mup[i];
                #pragma unroll
                for (int k = 0; k < PD; ++k) acc += s.Kt[k][i] * s.r[k];
                s.mu[i] = acc;
                g_muf[bt * NS + i] = acc;
                if (t == T - 1) ob[i * (NS + 1)] = acc;
            }
        }
        TBAR(bar);
    }
}

// ============================ J PRECOMPUTE (fully parallel) ============================
__global__ __launch_bounds__(32, 1)
void jpre_kernel(const float* __restrict__ A)
{
    __shared__ __align__(16) float sl[NS][33];
    const int lane = threadIdx.x;
    const int b = blockIdx.x;
    const int t = blockIdx.y;                  // 0 .. T-2
    const size_t bt = (size_t)b * T + t;
    const float* Ag  = A      + bt * NS * NS;
    const float* Sfg = g_Sigf + bt * NS * NS;
    const float* Spg = g_Sigp + (bt + 1) * NS * NS;

    #pragma unroll
    for (int e = lane; e < NS * NS / 4; e += 32) {
        float4 v = ((const float4*)Ag)[e];
        int r = (4 * e) >> 5, c = (4 * e) & 31;
        sl[r][c] = v.x; sl[r][c + 1] = v.y; sl[r][c + 2] = v.z; sl[r][c + 3] = v.w;
    }
    float sf[NS];
    #pragma unroll
    for (int q = 0; q < 8; ++q) {
        float4 v = ((const float4*)(Sfg + lane * NS))[q];
        sf[4 * q] = v.x; sf[4 * q + 1] = v.y; sf[4 * q + 2] = v.z; sf[4 * q + 3] = v.w;
    }
    __syncwarp();
    float m[NS];
    #pragma unroll
    for (int r = 0; r < NS; ++r) {
        float a0 = 0.f, a1 = 0.f;
        #pragma unroll 8
        for (int k = 0; k < NS; k += 2) { a0 += sf[k] * sl[r][k]; a1 += sf[k + 1] * sl[r][k + 1]; }
        m[r] = a0 + a1;
    }
    __syncwarp();
    #pragma unroll
    for (int e = lane; e < NS * NS / 4; e += 32) {
        float4 v = ((const float4*)Spg)[e];
        int r = (4 * e) >> 5, c = (4 * e) & 31;
        sl[r][c] = v.x; sl[r][c + 1] = v.y; sl[r][c + 2] = v.z; sl[r][c + 3] = v.w;
    }
    __syncwarp();
    {
        const int i = lane;
        #pragma unroll 1
        for (int k = 0; k < NS; ++k) {
            float dkk = sl[k][k];
            float rs  = rsqrtf(dkk);
            __syncwarp();
            if (i == k) { sl[k][k] = dkk * rs; sl[k][32] = rs; }
            if (i > k) sl[i][k] *= rs;
            __syncwarp();
            if (i > k) {
                float lik = sl[i][k];
                for (int j2 = k + 1; j2 <= i; ++j2) sl[i][j2] -= lik * sl[j2][k];
            }
            __syncwarp();
        }
    }
    float x[NS];
    #pragma unroll
    for (int r = 0; r < NS; ++r) {
        float a0 = m[r], a1 = 0.f;
        #pragma unroll
        for (int k = 0; k < r; ++k) {
            if (k & 1) a1 += sl[r][k] * x[k];
            else       a0 -= sl[r][k] * x[k];
        }
        x[r] = (a0 - a1) * sl[r][32];
    }
    #pragma unroll
    for (int r = NS - 1; r >= 0; --r) {
        float a0 = x[r], a1 = 0.f;
        #pragma unroll
        for (int k = r + 1; k < NS; ++k) {
            if (k & 1) a1 += sl[k][r] * x[k];
            else       a0 -= sl[k][r] * x[k];
        }
        x[r] = (a0 - a1) * sl[r][32];
    }
    float* Jg = g_J + bt * NS * NS;
    #pragma unroll
    for (int k = 0; k < NS; ++k) Jg[k * NS + lane] = x[k];
}

// ============================ BACKWARD SMOOTHER (2 teams / CTA) ============================
__global__ __launch_bounds__(512, 1)
void bwd_kernel(float* __restrict__ out)
{
    extern __shared__ __align__(16) char dyn[];
    __shared__ unsigned char mapR[136], mapC[136];

    const int tid  = threadIdx.x;
    const int team = tid >> 8, rt = tid & 255;
    const int b    = blockIdx.x * 2 + team;
    const int bar  = 1 + team;
    BwdS& s = ((BwdS*)dyn)[team];
    const int tr = rt >> 4, tc = rt & 15;

    if (tid == 0) {
        int e = 0;
        for (int r = 0; r < 16; ++r)
            for (int c = r; c < 16; ++c) { mapR[e] = (unsigned char)r; mapC[e] = (unsigned char)c; ++e; }
    }
    {
        const int t0 = T - 2, p0 = t0 & 1;
        const size_t bt  = (size_t)b * T + t0;
        const size_t btL = (size_t)b * T + (T - 1);
        const float* Sfg = g_Sigf + bt * NS * NS;
        const float* Spg = g_Sigp + (bt + 1) * NS * NS;
        const float* Jg  = g_J    + bt * NS * NS;
        const float* SfL = g_Sigf + btL * NS * NS;
        for (int e = rt; e < NS * NS; e += 256) {
            s.Sf[p0][e >> 5][e & 31] = Sfg[e];
            s.Sp[p0][e >> 5][e & 31] = Spg[e];
            s.Jt[p0][e >> 5][e & 31] = Jg[e];
            s.Sig[e >> 5][e & 31]    = SfL[e];
        }
        if (rt < NS) { s.mufB[p0][rt] = g_muf[bt * NS + rt]; s.muP[(T - 1) & 1][rt] = g_muf[btL * NS + rt]; }
        else if (rt < 2 * NS) s.mupB[p0][rt - NS] = g_mup[(bt + 1) * NS + (rt - NS)];
    }
    __syncthreads();

    for (int t = T - 2; t >= 0; --t) {
        const size_t bt = (size_t)b * T + t;
        const int p = t & 1;
        float (*Jt)[ST] = s.Jt[p];
        float (*Sf)[ST] = s.Sf[p];
        float (*Sp)[ST] = s.Sp[p];
        float* ob = out + bt * (size_t)(NS * (NS + 1));

        // phaseA: T1^T = (J (Sig_s - Sp))^T
        {
            const int i0 = 2 * tr, j0 = 2 * tc;
            float c00 = 0.f, c01 = 0.f, c10 = 0.f, c11 = 0.f;
            #pragma unroll 8
            for (int k = 0; k < NS; ++k) {
                float2 a  = *(const float2*)&Jt[k][i0];
                float2 s1 = *(const float2*)&s.Sig[k][j0];
                float2 s2 = *(const float2*)&Sp[k][j0];
                float bx = s1.x - s2.x, by = s1.y - s2.y;
                c00 += a.x * bx; c01 += a.x * by; c10 += a.y * bx; c11 += a.y * by;
            }
            s.T1[j0][i0] = c00; s.T1[j0 + 1][i0] = c01; s.T1[j0][i0 + 1] = c10; s.T1[j0 + 1][i0 + 1] = c11;
        }
        TBAR(bar);

        // phaseB: Sig_n = sym(Sf + T1 J^T) [136] ; mu_n [32] ; prefetch t-1 [88]
        if (rt < 136) {
            const int i0 = 2 * mapR[rt], j0 = 2 * mapC[rt];
            float c00 = Sf[i0][j0],     c01 = Sf[i0][j0 + 1];
            float c10 = Sf[i0 + 1][j0], c11 = Sf[i0 + 1][j0 + 1];
            #pragma unroll 8
            for (int k = 0; k < NS; ++k) {
                float2 a  = *(const float2*)&s.T1[k][i0];
                float2 bb = *(const float2*)&Jt[k][j0];
                c00 += a.x * bb.x; c01 += a.x * bb.y; c10 += a.y * bb.x; c11 += a.y * bb.y;
            }
            if (i0 == j0) { float av = 0.5f * (c01 + c10); c01 = av; c10 = av; }
            s.Sig[i0][j0] = c00; s.Sig[i0][j0 + 1] = c01; s.Sig[i0 + 1][j0] = c10; s.Sig[i0 + 1][j0 + 1] = c11;
            ob[i0 * (NS + 1) + 1 + j0] = c00; ob[i0 * (NS + 1) + 2 + j0] = c01;
            ob[(i0 + 1) * (NS + 1) + 1 + j0] = c10; ob[(i0 + 1) * (NS + 1) + 2 + j0] = c11;
            if (i0 != j0) {
                s.Sig[j0][i0] = c00; s.Sig[j0 + 1][i0] = c01; s.Sig[j0][i0 + 1] = c10; s.Sig[j0 + 1][i0 + 1] = c11;
                ob[j0 * (NS + 1) + 1 + i0] = c00; ob[(j0 + 1) * (NS + 1) + 1 + i0] = c01;
                ob[j0 * (NS + 1) + 2 + i0] = c10; ob[(j0 + 1) * (NS + 1) + 2 + i0] = c11;
            }
        } else if (rt < 168) {
            const int i = rt - 136;
            float acc = s.mufB[p][i];
            #pragma unroll 8
            for (int k = 0; k < NS; ++k) acc += Jt[k][i] * (s.muP[p ^ 1][k] - s.mupB[p][k]);
            s.muP[p][i] = acc;
            ob[i * (NS + 1)] = acc;
        } else if (t > 0) {
            const int q = rt - 168;
            const size_t btm = bt - 1;
            const float* Sfg = g_Sigf + btm * NS * NS;
            const float* Spg = g_Sigp + bt * NS * NS;
            const float* Jg  = g_J    + btm * NS * NS;
            const int pn = p ^ 1;
            for (int e = q; e < NS * NS; e += 88) {
                s.Sf[pn][e >> 5][e & 31] = Sfg[e];
                s.Sp[pn][e >> 5][e & 31] = Spg[e];
                s.Jt[pn][e >> 5][e & 31] = Jg[e];
            }
            if (q < NS) s.mufB[pn][q] = g_muf[btm * NS + q];
            else if (q < 2 * NS) s.mupB[pn][q - NS] = g_mup[bt * NS + (q - NS)];
        }
        TBAR(bar);
    }
}

extern "C" void kernel_launch(void* const* d_in, const int* in_sizes, int n_in,
                              void* d_out, int out_size)
{
    const float* Y    = (const float*)d_in[0];
    const float* U    = (const float*)d_in[1];
    const float* A    = (const float*)d_in[2];
    const float* Bm   = (const float*)d_in[3];
    const float* C    = (const float*)d_in[4];
    const float* mu0  = (const float*)d_in[5];
    const float* Sig0 = (const float*)d_in[6];
    float* out = (float*)d_out;

    cudaFuncSetAttribute(fwd_kernel, cudaFuncAttributeMaxDynamicSharedMemorySize,
                         (int)(2 * sizeof(FwdS)));
    cudaFuncSetAttribute(bwd_kernel, cudaFuncAttributeMaxDynamicSharedMemorySize,
                         (int)(2 * sizeof(BwdS)));

    fwd_kernel<<<BATCH / 2, 512, 2 * sizeof(FwdS)>>>(Y, U, A, Bm, C, mu0, Sig0, out);
    jpre_kernel<<<dim3(BATCH, T - 1), 32>>>(A);
    bwd_kernel<<<BATCH / 2, 512, 2 * sizeof(BwdS)>>>(out);
}